// round 14
// baseline (speedup 1.0000x reference)
#include <cuda_runtime.h>
#include <cstdint>

#define NNODE 50000
#define NEDGE 800000
#define ETOT  850000   // num edges + self loops
#define CCH   64
#define LL    3
#define SLOPE 0.2f
#define WPB   4        // warps per block in layer kernel
#define CH    16       // edges per subchunk
#define PSTR  36       // partial-matrix row stride (floats): 16B-aligned, conflict-free

// ---- packed f32x2 helpers (FFMA2/FADD2/FMUL2 are PTX-only on sm_103a) ----
union F2 { float2 f; unsigned long long u; };
#define FMA2(d, a, b, c) \
    asm("fma.rn.f32x2 %0, %1, %2, %3;" : "=l"((d).u) : "l"((a).u), "l"((b).u), "l"((c).u))
#define ADD2(d, a, b) \
    asm("add.rn.f32x2 %0, %1, %2;" : "=l"((d).u) : "l"((a).u), "l"((b).u))
#define MUL2(d, a, b) \
    asm("mul.rn.f32x2 %0, %1, %2;" : "=l"((d).u) : "l"((a).u), "l"((b).u))
#define PACK2(d, lo, hi) \
    asm("mov.b64 %0, {%1, %2};" : "=l"((d).u) : "r"(__float_as_uint(lo)), "r"(__float_as_uint(hi)))

// ---------------- static scratch ----------------
__device__ int   g_rowptr[NNODE + 1];
__device__ int   g_count[NNODE];       // zero at load; re-zeroed by scan each call
__device__ int   g_rank[ETOT];         // per-edge arrival rank within its dst
__device__ int   g_src[ETOT];          // src*CCH per CSR slot (grouped by dst)
__device__ float g_h0[NNODE * CCH];
__device__ float g_h1[NNODE * CCH];

// ---------------- CSR build (8 edges/thread, 8 atomics in flight) ------------
__global__ void hist_kernel(const int* __restrict__ ei) {
    int i = blockIdx.x * blockDim.x + threadIdx.x;
    if (i >= ETOT / 8) return;
    int base = 8 * i;
    int d[8];
    if (base < NEDGE) {          // NEDGE % 8 == 0: block never straddles
        int4 a = *(const int4*)(ei + NEDGE + base);
        int4 b = *(const int4*)(ei + NEDGE + base + 4);
        d[0] = a.x; d[1] = a.y; d[2] = a.z; d[3] = a.w;
        d[4] = b.x; d[5] = b.y; d[6] = b.z; d[7] = b.w;
    } else {
#pragma unroll
        for (int k = 0; k < 8; k++) d[k] = base - NEDGE + k;
    }
    int r[8];
#pragma unroll
    for (int k = 0; k < 8; k++) r[k] = atomicAdd(&g_count[d[k]], 1);
    *(int4*)(g_rank + base)     = make_int4(r[0], r[1], r[2], r[3]);
    *(int4*)(g_rank + base + 4) = make_int4(r[4], r[5], r[6], r[7]);
}

// single-block warp-shuffle scan (exclusive) -> g_rowptr; re-zeroes g_count
__global__ void scan_kernel() {
    __shared__ int wsum[33];
    __shared__ int carry_s;
    int tid = threadIdx.x, lane = tid & 31, wid = tid >> 5;
    if (tid == 0) carry_s = 0;
    __syncthreads();
    for (int base = 0; base < NNODE; base += 1024) {
        int i = base + tid;
        int v = (i < NNODE) ? g_count[i] : 0;
        int incl = v;
#pragma unroll
        for (int off = 1; off < 32; off <<= 1) {
            int t = __shfl_up_sync(0xffffffffu, incl, off);
            if (lane >= off) incl += t;
        }
        if (lane == 31) wsum[wid] = incl;
        __syncthreads();
        if (wid == 0) {
            int w = wsum[lane];
            int wincl = w;
#pragma unroll
            for (int off = 1; off < 32; off <<= 1) {
                int t = __shfl_up_sync(0xffffffffu, wincl, off);
                if (lane >= off) wincl += t;
            }
            wsum[lane] = wincl - w;
            if (lane == 31) wsum[32] = wincl;
        }
        __syncthreads();
        if (i < NNODE) {
            g_rowptr[i] = carry_s + wsum[wid] + incl - v;
            g_count[i] = 0;
        }
        __syncthreads();
        if (tid == 0) carry_s += wsum[32];
        __syncthreads();
    }
    if (threadIdx.x == 0) g_rowptr[NNODE] = ETOT;
}

// atomic-free scatter: position = rowptr[dst] + rank; stores src*CCH
__global__ void scatter_kernel(const int* __restrict__ ei) {
    int i = blockIdx.x * blockDim.x + threadIdx.x;
    if (i >= ETOT / 8) return;
    int base = 8 * i;
    int s[8], d[8];
    if (base < NEDGE) {
        int4 sa = *(const int4*)(ei + base);
        int4 sb = *(const int4*)(ei + base + 4);
        int4 da = *(const int4*)(ei + NEDGE + base);
        int4 db = *(const int4*)(ei + NEDGE + base + 4);
        s[0] = sa.x; s[1] = sa.y; s[2] = sa.z; s[3] = sa.w;
        s[4] = sb.x; s[5] = sb.y; s[6] = sb.z; s[7] = sb.w;
        d[0] = da.x; d[1] = da.y; d[2] = da.z; d[3] = da.w;
        d[4] = db.x; d[5] = db.y; d[6] = db.z; d[7] = db.w;
    } else {
#pragma unroll
        for (int k = 0; k < 8; k++) { s[k] = base - NEDGE + k; d[k] = s[k]; }
    }
    int4 ra = *(const int4*)(g_rank + base);
    int4 rb = *(const int4*)(g_rank + base + 4);
    int r[8] = {ra.x, ra.y, ra.z, ra.w, rb.x, rb.y, rb.z, rb.w};
#pragma unroll
    for (int k = 0; k < 8; k++)
        g_src[g_rowptr[d[k]] + r[k]] = s[k] * CCH;
}

// ---- fused layer: inline partial logits, smem partial-combine, reg agg -----
// Lane (half,sub) owns channels [4sub,4sub+4) and rows {2j+half}. Partial
// leaky-dot computed inline with the gather (att/xd slices live in regs);
// 16x16 partial matrix combined through smem (conflict-free); aggregation
// from the gathered registers. v zero-init hoisted out of the chunk loop
// (stale values safe: invalid edges get weight 0; stale partials never exp'd).
__global__ void __launch_bounds__(WPB * 32) layer_kernel(
    int layer, const float* __restrict__ x0,
    const float* __restrict__ att, const float* __restrict__ bias,
    float* __restrict__ out)
{
    __shared__ float part_s[WPB][CH * PSTR];

    int tid = threadIdx.x, lane = tid & 31, wid = tid >> 5;
    int node = blockIdx.x * WPB + wid;
    if (node >= NNODE) return;

    const float* x = (layer == 0) ? x0 : ((layer == 1) ? g_h0 : g_h1);
    int half = lane >> 4;       // row parity
    int sub  = lane & 15;       // channel group [4sub, 4sub+4)

    // per-lane constant slices (registers)
    float4 af = *(const float4*)(att + layer * 2 * CCH + sub * 4);
    float4 bf = *(const float4*)(att + layer * 2 * CCH + CCH + sub * 4);
    float4 xd = *(const float4*)(x + (size_t)node * CCH + sub * 4);

    F2 alo, ahi, blo, bhi, dlo, dhi, c02;
    alo.f = make_float2(af.x, af.y); ahi.f = make_float2(af.z, af.w);
    blo.f = make_float2(bf.x, bf.y); bhi.f = make_float2(bf.z, bf.w);
    dlo.f = make_float2(xd.x, xd.y); dhi.f = make_float2(xd.z, xd.w);
    c02.f = make_float2(SLOPE, SLOPE);

    float s0 = 0.f, s1 = 0.f;
    F2 acc0lo, acc0hi, acc1lo, acc1hi;
    acc0lo.f = make_float2(0.f, 0.f); acc0hi.f = make_float2(0.f, 0.f);
    acc1lo.f = make_float2(0.f, 0.f); acc1hi.f = make_float2(0.f, 0.f);

    int start = g_rowptr[node];
    int end   = g_rowptr[node + 1];
    float* ps = part_s[wid];

    // zero-init once per node (hoisted); stale values across chunks are safe
    float4 v[8];
#pragma unroll
    for (int j = 0; j < 8; j++) v[j] = make_float4(0.f, 0.f, 0.f, 0.f);

    for (int cs = start; cs < end; cs += 32) {
        int sidx32 = (cs + lane < end) ? g_src[cs + lane] : 0;
        int rem = end - cs;

#pragma unroll
        for (int sc = 0; sc < 2; sc++) {
            int off = sc * CH;
            if (off >= rem) break;
            int cnt = min(CH, rem - off);

            __syncwarp();  // WAR vs previous subchunk's combine LDS
            // gather own slice of 8 own-parity rows; partial logit inline
#pragma unroll
            for (int j = 0; j < 8; j++) {
                int r = 2 * j + half;
                int sk = __shfl_sync(0xffffffffu, sidx32, off + r);
                if (r < cnt) v[j] = *(const float4*)(x + sk + sub * 4);
                F2 vlo, vhi, zlo, zhi, mlo, mhi, tlo, thi, q0, q1;
                vlo.f = make_float2(v[j].x, v[j].y);
                vhi.f = make_float2(v[j].z, v[j].w);
                ADD2(zlo, vlo, dlo);
                ADD2(zhi, vhi, dhi);
                MUL2(mlo, zlo, c02);
                MUL2(mhi, zhi, c02);
                tlo.f.x = fmaxf(zlo.f.x, mlo.f.x);
                tlo.f.y = fmaxf(zlo.f.y, mlo.f.y);
                thi.f.x = fmaxf(zhi.f.x, mhi.f.x);
                thi.f.y = fmaxf(zhi.f.y, mhi.f.y);
                q0.f = make_float2(0.f, 0.f);
                q1.f = make_float2(0.f, 0.f);
                FMA2(q0, tlo, alo, q0);
                FMA2(q0, thi, ahi, q0);
                FMA2(q1, tlo, blo, q1);
                FMA2(q1, thi, bhi, q1);
                // (p0,p1) partial for edge r at slice sub
                *(float2*)&ps[r * PSTR + sub * 2] =
                    make_float2(q0.f.x + q0.f.y, q1.f.x + q1.f.y);
            }
            __syncwarp();

            // combine: lane handles edge `sub`; sums 8 partials of its half
            const float4* pp = (const float4*)&ps[sub * PSTR + half * 16];
            float4 c0 = pp[0], c1 = pp[1], c2 = pp[2], c3 = pp[3];
            F2 t0, t1, t2, t3, u0, u1, qs;
            t0.f = make_float2(c0.x, c0.y); t1.f = make_float2(c0.z, c0.w);
            t2.f = make_float2(c1.x, c1.y); t3.f = make_float2(c1.z, c1.w);
            ADD2(u0, t0, t1);
            ADD2(u1, t2, t3);
            ADD2(u0, u0, u1);
            t0.f = make_float2(c2.x, c2.y); t1.f = make_float2(c2.z, c2.w);
            t2.f = make_float2(c3.x, c3.y); t3.f = make_float2(c3.z, c3.w);
            ADD2(t0, t0, t1);
            ADD2(t2, t2, t3);
            ADD2(t0, t0, t2);
            ADD2(qs, u0, t0);
            float p0 = qs.f.x + __shfl_xor_sync(0xffffffffu, qs.f.x, 16);
            float p1 = qs.f.y + __shfl_xor_sync(0xffffffffu, qs.f.y, 16);

            // logits bounded (|p| < ~10): exp without max subtraction exact
            float w0 = (sub < cnt) ? __expf(p0) : 0.f;
            float w1 = (sub < cnt) ? __expf(p1) : 0.f;
            s0 += w0;                       // dup across halves -> 2S, folded
            s1 += w1;

            // aggregate own rows from registers; weight via one shfl per row
#pragma unroll
            for (int j = 0; j < 8; j++) {
                int e = 2 * j + half;
                float wk0 = __shfl_sync(0xffffffffu, w0, e);
                float wk1 = __shfl_sync(0xffffffffu, w1, e);
                F2 wp0, wp1, vlo, vhi;
                PACK2(wp0, wk0, wk0);
                PACK2(wp1, wk1, wk1);
                vlo.f = make_float2(v[j].x, v[j].y);
                vhi.f = make_float2(v[j].z, v[j].w);
                FMA2(acc0lo, wp0, vlo, acc0lo);
                FMA2(acc0hi, wp0, vhi, acc0hi);
                FMA2(acc1lo, wp1, vlo, acc1lo);
                FMA2(acc1hi, wp1, vhi, acc1hi);
            }
        }
    }

    // heal parity split (channels [4sub,4sub+4) live in both halves)
    acc0lo.f.x += __shfl_xor_sync(0xffffffffu, acc0lo.f.x, 16);
    acc0lo.f.y += __shfl_xor_sync(0xffffffffu, acc0lo.f.y, 16);
    acc0hi.f.x += __shfl_xor_sync(0xffffffffu, acc0hi.f.x, 16);
    acc0hi.f.y += __shfl_xor_sync(0xffffffffu, acc0hi.f.y, 16);
    acc1lo.f.x += __shfl_xor_sync(0xffffffffu, acc1lo.f.x, 16);
    acc1lo.f.y += __shfl_xor_sync(0xffffffffu, acc1lo.f.y, 16);
    acc1hi.f.x += __shfl_xor_sync(0xffffffffu, acc1hi.f.x, 16);
    acc1hi.f.y += __shfl_xor_sync(0xffffffffu, acc1hi.f.y, 16);

    // sum over 32 lanes = 2 * S (w duplicated across halves)
#pragma unroll
    for (int off = 16; off; off >>= 1) {
        s0 += __shfl_xor_sync(0xffffffffu, s0, off);
        s1 += __shfl_xor_sync(0xffffffffu, s1, off);
    }
    float inv0 = 1.0f / (s0 + 2e-16f);          // = 0.5 / S (head-mean folded)
    float inv1 = 1.0f / (s1 + 2e-16f);

    if (half == 0) {
        float4 bsv = *(const float4*)(bias + layer * CCH + sub * 4);
        float4 o;
        o.x = acc0lo.f.x * inv0 + acc1lo.f.x * inv1 + bsv.x;
        o.y = acc0lo.f.y * inv0 + acc1lo.f.y * inv1 + bsv.y;
        o.z = acc0hi.f.x * inv0 + acc1hi.f.x * inv1 + bsv.z;
        o.w = acc0hi.f.y * inv0 + acc1hi.f.y * inv1 + bsv.w;

        size_t ofs = (size_t)node * CCH + sub * 4;
        if (layer < 2) {
            float* h = (layer == 0) ? g_h0 : g_h1;
            *(float4*)(h + ofs) = o;
        }
        float4* op = (float4*)(out + ofs);
        if (layer == 0) {
            // out = feats[0] + h1 (out buffer is poisoned; do not read it)
            *op = make_float4(xd.x + o.x, xd.y + o.y, xd.z + o.z, xd.w + o.w);
        } else if (layer == 1) {
            float4 ov = *op;
            ov.x += o.x; ov.y += o.y; ov.z += o.z; ov.w += o.w;
            *op = ov;
        } else {        // fused final mean over {x, h1, h2, h3}
            float4 ov = *op;
            ov.x = (ov.x + o.x) * 0.25f;
            ov.y = (ov.y + o.y) * 0.25f;
            ov.z = (ov.z + o.z) * 0.25f;
            ov.w = (ov.w + o.w) * 0.25f;
            *op = ov;
        }
    }
}

// ---------------- launch ----------------
extern "C" void kernel_launch(void* const* d_in, const int* in_sizes, int n_in,
                              void* d_out, int out_size) {
    const float* x    = (const float*)d_in[0];
    const int*   ei   = (const int*)d_in[1];
    const float* att  = (const float*)d_in[2];
    const float* bias = (const float*)d_in[3];
    float* out = (float*)d_out;

    hist_kernel<<<(ETOT / 8 + 255) / 256, 256>>>(ei);
    scan_kernel<<<1, 1024>>>();
    scatter_kernel<<<(ETOT / 8 + 255) / 256, 256>>>(ei);

    dim3 grd((NNODE + WPB - 1) / WPB);
    for (int l = 0; l < LL; l++)
        layer_kernel<<<grd, WPB * 32>>>(l, x, att, bias, out);
}

// round 15
// speedup vs baseline: 1.4068x; 1.4068x over previous
#include <cuda_runtime.h>
#include <cstdint>

#define NNODE 50000
#define NEDGE 800000
#define ETOT  850000   // num edges + self loops
#define CCH   64
#define LL    3
#define SLOPE 0.2f
#define WPB   4        // warps per block in layer kernel
#define CH    16       // edges per subchunk
#define PSTR  36       // partial-matrix row stride (floats): 16B-aligned, conflict-free

// ---- packed f32x2 helpers (FFMA2/FADD2/FMUL2 are PTX-only on sm_103a) ----
union F2 { float2 f; unsigned long long u; };
#define FMA2(d, a, b, c) \
    asm("fma.rn.f32x2 %0, %1, %2, %3;" : "=l"((d).u) : "l"((a).u), "l"((b).u), "l"((c).u))
#define ADD2(d, a, b) \
    asm("add.rn.f32x2 %0, %1, %2;" : "=l"((d).u) : "l"((a).u), "l"((b).u))
#define MUL2(d, a, b) \
    asm("mul.rn.f32x2 %0, %1, %2;" : "=l"((d).u) : "l"((a).u), "l"((b).u))
#define PACK2(d, lo, hi) \
    asm("mov.b64 %0, {%1, %2};" : "=l"((d).u) : "r"(__float_as_uint(lo)), "r"(__float_as_uint(hi)))

// ---------------- static scratch ----------------
__device__ int   g_rowptr[NNODE + 1];
__device__ int   g_count[NNODE];       // zero at load; re-zeroed by scan each call
__device__ int   g_rank[ETOT];         // per-edge arrival rank within its dst
__device__ int   g_src[ETOT];          // src*CCH per CSR slot (grouped by dst)
__device__ float g_h0[NNODE * CCH];
__device__ float g_h1[NNODE * CCH];

// ---------------- CSR build (8 edges/thread, 8 atomics in flight) ------------
__global__ void hist_kernel(const int* __restrict__ ei) {
    int i = blockIdx.x * blockDim.x + threadIdx.x;
    if (i >= ETOT / 8) return;
    int base = 8 * i;
    int d[8];
    if (base < NEDGE) {          // NEDGE % 8 == 0: block never straddles
        int4 a = *(const int4*)(ei + NEDGE + base);
        int4 b = *(const int4*)(ei + NEDGE + base + 4);
        d[0] = a.x; d[1] = a.y; d[2] = a.z; d[3] = a.w;
        d[4] = b.x; d[5] = b.y; d[6] = b.z; d[7] = b.w;
    } else {
#pragma unroll
        for (int k = 0; k < 8; k++) d[k] = base - NEDGE + k;
    }
    int r[8];
#pragma unroll
    for (int k = 0; k < 8; k++) r[k] = atomicAdd(&g_count[d[k]], 1);
    *(int4*)(g_rank + base)     = make_int4(r[0], r[1], r[2], r[3]);
    *(int4*)(g_rank + base + 4) = make_int4(r[4], r[5], r[6], r[7]);
}

// single-block scan, 4 elements/thread (int4) -> g_rowptr; re-zeroes g_count.
// 13 block-iterations instead of 49; same barrier structure per iteration.
__global__ void scan_kernel() {
    __shared__ int wsum[33];
    __shared__ int carry_s;
    int tid = threadIdx.x, lane = tid & 31, wid = tid >> 5;
    if (tid == 0) carry_s = 0;
    __syncthreads();
    for (int base = 0; base < NNODE; base += 4096) {
        int i4 = base + 4 * tid;
        int4 c = make_int4(0, 0, 0, 0);
        if (i4 < NNODE)                     // NNODE % 4 == 0: full int4 or none
            c = *(const int4*)(g_count + i4);
        int tsum = c.x + c.y + c.z + c.w;
        int incl = tsum;
#pragma unroll
        for (int off = 1; off < 32; off <<= 1) {
            int t = __shfl_up_sync(0xffffffffu, incl, off);
            if (lane >= off) incl += t;
        }
        if (lane == 31) wsum[wid] = incl;
        __syncthreads();
        if (wid == 0) {
            int w = wsum[lane];
            int wincl = w;
#pragma unroll
            for (int off = 1; off < 32; off <<= 1) {
                int t = __shfl_up_sync(0xffffffffu, wincl, off);
                if (lane >= off) wincl += t;
            }
            wsum[lane] = wincl - w;
            if (lane == 31) wsum[32] = wincl;
        }
        __syncthreads();
        if (i4 < NNODE) {
            int excl = carry_s + wsum[wid] + incl - tsum;
            int4 rp;
            rp.x = excl;
            rp.y = rp.x + c.x;
            rp.z = rp.y + c.y;
            rp.w = rp.z + c.z;
            *(int4*)(g_rowptr + i4) = rp;
            *(int4*)(g_count + i4) = make_int4(0, 0, 0, 0);
        }
        __syncthreads();
        if (tid == 0) carry_s += wsum[32];
        __syncthreads();
    }
    if (threadIdx.x == 0) g_rowptr[NNODE] = ETOT;
}

// atomic-free scatter: position = rowptr[dst] + rank; stores src*CCH
__global__ void scatter_kernel(const int* __restrict__ ei) {
    int i = blockIdx.x * blockDim.x + threadIdx.x;
    if (i >= ETOT / 8) return;
    int base = 8 * i;
    int s[8], d[8];
    if (base < NEDGE) {
        int4 sa = *(const int4*)(ei + base);
        int4 sb = *(const int4*)(ei + base + 4);
        int4 da = *(const int4*)(ei + NEDGE + base);
        int4 db = *(const int4*)(ei + NEDGE + base + 4);
        s[0] = sa.x; s[1] = sa.y; s[2] = sa.z; s[3] = sa.w;
        s[4] = sb.x; s[5] = sb.y; s[6] = sb.z; s[7] = sb.w;
        d[0] = da.x; d[1] = da.y; d[2] = da.z; d[3] = da.w;
        d[4] = db.x; d[5] = db.y; d[6] = db.z; d[7] = db.w;
    } else {
#pragma unroll
        for (int k = 0; k < 8; k++) { s[k] = base - NEDGE + k; d[k] = s[k]; }
    }
    int4 ra = *(const int4*)(g_rank + base);
    int4 rb = *(const int4*)(g_rank + base + 4);
    int r[8] = {ra.x, ra.y, ra.z, ra.w, rb.x, rb.y, rb.z, rb.w};
#pragma unroll
    for (int k = 0; k < 8; k++)
        g_src[g_rowptr[d[k]] + r[k]] = s[k] * CCH;
}

// ---- fused layer: inline partial logits, smem partial-combine, reg agg -----
// EXACT 221.5us anchor code: v[] declared + zero-initialized inside the chunk
// loop (fresh registers each chunk -> ptxas batches the 8 LDG.128s).
__global__ void __launch_bounds__(WPB * 32) layer_kernel(
    int layer, const float* __restrict__ x0,
    const float* __restrict__ att, const float* __restrict__ bias,
    float* __restrict__ out)
{
    __shared__ float part_s[WPB][CH * PSTR];

    int tid = threadIdx.x, lane = tid & 31, wid = tid >> 5;
    int node = blockIdx.x * WPB + wid;
    if (node >= NNODE) return;

    const float* x = (layer == 0) ? x0 : ((layer == 1) ? g_h0 : g_h1);
    int half = lane >> 4;       // row parity
    int sub  = lane & 15;       // channel group [4sub, 4sub+4)

    // per-lane constant slices (registers)
    float4 af = *(const float4*)(att + layer * 2 * CCH + sub * 4);
    float4 bf = *(const float4*)(att + layer * 2 * CCH + CCH + sub * 4);
    float4 xd = *(const float4*)(x + (size_t)node * CCH + sub * 4);

    F2 alo, ahi, blo, bhi, dlo, dhi, c02;
    alo.f = make_float2(af.x, af.y); ahi.f = make_float2(af.z, af.w);
    blo.f = make_float2(bf.x, bf.y); bhi.f = make_float2(bf.z, bf.w);
    dlo.f = make_float2(xd.x, xd.y); dhi.f = make_float2(xd.z, xd.w);
    c02.f = make_float2(SLOPE, SLOPE);

    float s0 = 0.f, s1 = 0.f;
    F2 acc0lo, acc0hi, acc1lo, acc1hi;
    acc0lo.f = make_float2(0.f, 0.f); acc0hi.f = make_float2(0.f, 0.f);
    acc1lo.f = make_float2(0.f, 0.f); acc1hi.f = make_float2(0.f, 0.f);

    int start = g_rowptr[node];
    int end   = g_rowptr[node + 1];
    float* ps = part_s[wid];

    for (int cs = start; cs < end; cs += 32) {
        int sidx32 = (cs + lane < end) ? g_src[cs + lane] : 0;
        int rem = end - cs;

#pragma unroll
        for (int sc = 0; sc < 2; sc++) {
            int off = sc * CH;
            if (off >= rem) break;
            int cnt = min(CH, rem - off);

            __syncwarp();  // WAR vs previous subchunk's combine LDS
            // gather own slice of 8 own-parity rows; partial logit inline
            float4 v[8];
#pragma unroll
            for (int j = 0; j < 8; j++) {
                int r = 2 * j + half;
                int sk = __shfl_sync(0xffffffffu, sidx32, off + r);
                v[j] = make_float4(0.f, 0.f, 0.f, 0.f);
                if (r < cnt) v[j] = *(const float4*)(x + sk + sub * 4);
                F2 vlo, vhi, zlo, zhi, mlo, mhi, tlo, thi, q0, q1;
                vlo.f = make_float2(v[j].x, v[j].y);
                vhi.f = make_float2(v[j].z, v[j].w);
                ADD2(zlo, vlo, dlo);
                ADD2(zhi, vhi, dhi);
                MUL2(mlo, zlo, c02);
                MUL2(mhi, zhi, c02);
                tlo.f.x = fmaxf(zlo.f.x, mlo.f.x);
                tlo.f.y = fmaxf(zlo.f.y, mlo.f.y);
                thi.f.x = fmaxf(zhi.f.x, mhi.f.x);
                thi.f.y = fmaxf(zhi.f.y, mhi.f.y);
                q0.f = make_float2(0.f, 0.f);
                q1.f = make_float2(0.f, 0.f);
                FMA2(q0, tlo, alo, q0);
                FMA2(q0, thi, ahi, q0);
                FMA2(q1, tlo, blo, q1);
                FMA2(q1, thi, bhi, q1);
                // (p0,p1) partial for edge r at slice sub
                *(float2*)&ps[r * PSTR + sub * 2] =
                    make_float2(q0.f.x + q0.f.y, q1.f.x + q1.f.y);
            }
            __syncwarp();

            // combine: lane handles edge `sub`; sums 8 partials of its half
            const float4* pp = (const float4*)&ps[sub * PSTR + half * 16];
            float4 c0 = pp[0], c1 = pp[1], c2 = pp[2], c3 = pp[3];
            F2 t0, t1, t2, t3, u0, u1, qs;
            t0.f = make_float2(c0.x, c0.y); t1.f = make_float2(c0.z, c0.w);
            t2.f = make_float2(c1.x, c1.y); t3.f = make_float2(c1.z, c1.w);
            ADD2(u0, t0, t1);
            ADD2(u1, t2, t3);
            ADD2(u0, u0, u1);
            t0.f = make_float2(c2.x, c2.y); t1.f = make_float2(c2.z, c2.w);
            t2.f = make_float2(c3.x, c3.y); t3.f = make_float2(c3.z, c3.w);
            ADD2(t0, t0, t1);
            ADD2(t2, t2, t3);
            ADD2(t0, t0, t2);
            ADD2(qs, u0, t0);
            float p0 = qs.f.x + __shfl_xor_sync(0xffffffffu, qs.f.x, 16);
            float p1 = qs.f.y + __shfl_xor_sync(0xffffffffu, qs.f.y, 16);

            // logits bounded (|p| < ~10): exp without max subtraction exact
            float w0 = (sub < cnt) ? __expf(p0) : 0.f;
            float w1 = (sub < cnt) ? __expf(p1) : 0.f;
            s0 += w0;                       // dup across halves -> 2S, folded
            s1 += w1;

            // aggregate own rows from registers; weight via one shfl per row
#pragma unroll
            for (int j = 0; j < 8; j++) {
                int e = 2 * j + half;
                float wk0 = __shfl_sync(0xffffffffu, w0, e);
                float wk1 = __shfl_sync(0xffffffffu, w1, e);
                F2 wp0, wp1, vlo, vhi;
                PACK2(wp0, wk0, wk0);
                PACK2(wp1, wk1, wk1);
                vlo.f = make_float2(v[j].x, v[j].y);
                vhi.f = make_float2(v[j].z, v[j].w);
                FMA2(acc0lo, wp0, vlo, acc0lo);
                FMA2(acc0hi, wp0, vhi, acc0hi);
                FMA2(acc1lo, wp1, vlo, acc1lo);
                FMA2(acc1hi, wp1, vhi, acc1hi);
            }
        }
    }

    // heal parity split (channels [4sub,4sub+4) live in both halves)
    acc0lo.f.x += __shfl_xor_sync(0xffffffffu, acc0lo.f.x, 16);
    acc0lo.f.y += __shfl_xor_sync(0xffffffffu, acc0lo.f.y, 16);
    acc0hi.f.x += __shfl_xor_sync(0xffffffffu, acc0hi.f.x, 16);
    acc0hi.f.y += __shfl_xor_sync(0xffffffffu, acc0hi.f.y, 16);
    acc1lo.f.x += __shfl_xor_sync(0xffffffffu, acc1lo.f.x, 16);
    acc1lo.f.y += __shfl_xor_sync(0xffffffffu, acc1lo.f.y, 16);
    acc1hi.f.x += __shfl_xor_sync(0xffffffffu, acc1hi.f.x, 16);
    acc1hi.f.y += __shfl_xor_sync(0xffffffffu, acc1hi.f.y, 16);

    // sum over 32 lanes = 2 * S (w duplicated across halves)
#pragma unroll
    for (int off = 16; off; off >>= 1) {
        s0 += __shfl_xor_sync(0xffffffffu, s0, off);
        s1 += __shfl_xor_sync(0xffffffffu, s1, off);
    }
    float inv0 = 1.0f / (s0 + 2e-16f);          // = 0.5 / S (head-mean folded)
    float inv1 = 1.0f / (s1 + 2e-16f);

    if (half == 0) {
        float4 bsv = *(const float4*)(bias + layer * CCH + sub * 4);
        float4 o;
        o.x = acc0lo.f.x * inv0 + acc1lo.f.x * inv1 + bsv.x;
        o.y = acc0lo.f.y * inv0 + acc1lo.f.y * inv1 + bsv.y;
        o.z = acc0hi.f.x * inv0 + acc1hi.f.x * inv1 + bsv.z;
        o.w = acc0hi.f.y * inv0 + acc1hi.f.y * inv1 + bsv.w;

        size_t ofs = (size_t)node * CCH + sub * 4;
        if (layer < 2) {
            float* h = (layer == 0) ? g_h0 : g_h1;
            *(float4*)(h + ofs) = o;
        }
        float4* op = (float4*)(out + ofs);
        if (layer == 0) {
            // out = feats[0] + h1 (out buffer is poisoned; do not read it)
            *op = make_float4(xd.x + o.x, xd.y + o.y, xd.z + o.z, xd.w + o.w);
        } else if (layer == 1) {
            float4 ov = *op;
            ov.x += o.x; ov.y += o.y; ov.z += o.z; ov.w += o.w;
            *op = ov;
        } else {        // fused final mean over {x, h1, h2, h3}
            float4 ov = *op;
            ov.x = (ov.x + o.x) * 0.25f;
            ov.y = (ov.y + o.y) * 0.25f;
            ov.z = (ov.z + o.z) * 0.25f;
            ov.w = (ov.w + o.w) * 0.25f;
            *op = ov;
        }
    }
}

// ---------------- launch ----------------
extern "C" void kernel_launch(void* const* d_in, const int* in_sizes, int n_in,
                              void* d_out, int out_size) {
    const float* x    = (const float*)d_in[0];
    const int*   ei   = (const int*)d_in[1];
    const float* att  = (const float*)d_in[2];
    const float* bias = (const float*)d_in[3];
    float* out = (float*)d_out;

    hist_kernel<<<(ETOT / 8 + 255) / 256, 256>>>(ei);
    scan_kernel<<<1, 1024>>>();
    scatter_kernel<<<(ETOT / 8 + 255) / 256, 256>>>(ei);

    dim3 grd((NNODE + WPB - 1) / WPB);
    for (int l = 0; l < LL; l++)
        layer_kernel<<<grd, WPB * 32>>>(l, x, att, bias, out);
}